// round 6
// baseline (speedup 1.0000x reference)
#include <cuda_runtime.h>

// ---------------------------------------------------------------------------
// MIND loss, fully fused, single kernel. R6:
//  - role-specialized warps: warps 0-1 = row-stage only (incl. 64 overflow
//    units), warps 2-7 = row unit + all column/epilogue work (rows 11/11/10)
//    -> balanced per-warp time at each __syncthreads
//  - last-CTA global reduction folded in (deterministic fixed-order sum)
//  - pred/gt packed into f32x2 (FFMA2); conflict-free 64-bit smem (81/67)
//  - M/max(M) == exp((Dmin - D)/V) -> two passes over the 99 shifts
// ---------------------------------------------------------------------------

typedef unsigned long long u64;

namespace {
constexpr int HIMG = 384;
constexpr int WIMG = 384;
constexpr int BATCH = 4;
constexpr int INNER = 370;          // 384 - 2*7
constexpr int TILE_H = 32;
constexpr int TILE_W = 64;
constexpr int CHP = 40;             // conv-support rows (38 used + 2 pad)
constexpr int RH = 49;              // img tile rows
constexpr int RW = 79;              // img tile cols
constexpr int IP2 = 81;             // img pitch (float2 units, odd)
constexpr int RP2 = 67;             // row-buf pitch (float2 units, odd)
constexpr int NTHREADS = 256;
constexpr int TILES_X = 6;          // 6*64 = 384 >= 370
constexpr int TILES_Y = 12;         // 12*32 = 384 >= 370
constexpr int NCTAS = BATCH * TILES_X * TILES_Y;   // 288 -> one wave @ occ 2
constexpr int SMEM_U64 = RH * IP2 + 2 * CHP * RP2;
constexpr int SMEM_BYTES = SMEM_U64 * 8;           // 74632 B

constexpr double E98 = 0.32465246735834974;   // exp(-9/8)
constexpr double E48 = 0.60653065971263342;   // exp(-4/8)
constexpr double E18 = 0.88249690258459546;   // exp(-1/8)
constexpr double TPS = 25.132741228718345;    // 8*pi
constexpr float GX0 = (float)E98;
constexpr float GX1 = (float)E48;
constexpr float GX2 = (float)E18;             // center tap == 1
constexpr float GY0 = (float)(E98 / TPS);
constexpr float GY1 = (float)(E48 / TPS);
constexpr float GY2 = (float)(E18 / TPS);
constexpr float GY3 = (float)(1.0 / TPS);
}  // namespace

__device__ float g_partials[NCTAS];
__device__ unsigned int g_count = 0;

// ---- packed f32x2 helpers (sm_100+) ----
__device__ __forceinline__ u64 bc2(float x) {
  u64 r; asm("mov.b64 %0,{%1,%1};" : "=l"(r) : "f"(x)); return r;
}
__device__ __forceinline__ u64 pk2(float a, float b) {
  u64 r; asm("mov.b64 %0,{%1,%2};" : "=l"(r) : "f"(a), "f"(b)); return r;
}
__device__ __forceinline__ void up2(u64 v, float& a, float& b) {
  asm("mov.b64 {%0,%1},%2;" : "=f"(a), "=f"(b) : "l"(v));
}
__device__ __forceinline__ u64 f2sub(u64 a, u64 b) {
  u64 r; asm("sub.rn.f32x2 %0,%1,%2;" : "=l"(r) : "l"(a), "l"(b)); return r;
}
__device__ __forceinline__ u64 f2mul(u64 a, u64 b) {
  u64 r; asm("mul.rn.f32x2 %0,%1,%2;" : "=l"(r) : "l"(a), "l"(b)); return r;
}
__device__ __forceinline__ u64 f2add(u64 a, u64 b) {
  u64 r; asm("add.rn.f32x2 %0,%1,%2;" : "=l"(r) : "l"(a), "l"(b)); return r;
}
__device__ __forceinline__ u64 f2fma(u64 a, u64 b, u64 c) {
  u64 r; asm("fma.rn.f32x2 %0,%1,%2,%3;" : "=l"(r) : "l"(a), "l"(b), "l"(c));
  return r;
}

// Horizontal 7-tap conv over precomputed dsq -> 8 outputs.
__device__ __forceinline__ void hconv8(const u64 dsq[14], u64* __restrict__ pr,
                                       u64 gx0, u64 gx1, u64 gx2) {
#pragma unroll
  for (int c = 0; c < 8; c++) {
    u64 v = f2mul(gx0, dsq[c]);
    v = f2fma(gx1, dsq[c + 1], v);
    v = f2fma(gx2, dsq[c + 2], v);
    v = f2add(v, dsq[c + 3]);  // center tap weight == 1
    v = f2fma(gx2, dsq[c + 4], v);
    v = f2fma(gx1, dsq[c + 5], v);
    v = f2fma(gx0, dsq[c + 6], v);
    pr[c] = v;
  }
}

__device__ __forceinline__ void row_cached(const u64 pa[14],
                                           const u64* __restrict__ pb,
                                           u64* __restrict__ pr,
                                           u64 gx0, u64 gx1, u64 gx2) {
  u64 dsq[14];
#pragma unroll
  for (int k = 0; k < 14; k++) {
    u64 d = f2sub(pa[k], pb[k]);
    dsq[k] = f2mul(d, d);
  }
  hconv8(dsq, pr, gx0, gx1, gx2);
}

__device__ __forceinline__ void row_smem(const u64* __restrict__ pa,
                                         const u64* __restrict__ pb,
                                         u64* __restrict__ pr,
                                         u64 gx0, u64 gx1, u64 gx2) {
  u64 dsq[14];
#pragma unroll
  for (int k = 0; k < 14; k++) {
    u64 d = f2sub(pa[k], pb[k]);
    dsq[k] = f2mul(d, d);
  }
  hconv8(dsq, pr, gx0, gx1, gx2);
}

__device__ __forceinline__ u64 col7(const u64* rv, int i,
                                    u64 gy0, u64 gy1, u64 gy2, u64 gy3) {
  u64 v = f2mul(gy0, rv[i]);
  v = f2fma(gy1, rv[i + 1], v);
  v = f2fma(gy2, rv[i + 2], v);
  v = f2fma(gy3, rv[i + 3], v);
  v = f2fma(gy2, rv[i + 4], v);
  v = f2fma(gy1, rv[i + 5], v);
  v = f2fma(gy0, rv[i + 6], v);
  return v;
}

template <int N>
__device__ __forceinline__ void colA(const u64* __restrict__ bufc, int off,
                                     bool card, float* DmP, float* DmG,
                                     float* Vp, float* Vg,
                                     u64 gy0, u64 gy1, u64 gy2, u64 gy3) {
  u64 rv[N + 6];
#pragma unroll
  for (int i = 0; i < N + 6; i++) rv[i] = bufc[off + i * RP2];
#pragma unroll
  for (int i = 0; i < N; i++) {
    u64 D2 = col7(rv, i, gy0, gy1, gy2, gy3);
    float dp, dg; up2(D2, dp, dg);
    DmP[i] = fminf(DmP[i], dp);
    DmG[i] = fminf(DmG[i], dg);
    if (card) { Vp[i] += dp; Vg[i] += dg; }
  }
}

template <int N>
__device__ __forceinline__ float colB(const u64* __restrict__ bufc, int off,
                                      const u64* Dmin2, const u64* invV2,
                                      int py0, bool cOK,
                                      u64 gy0, u64 gy1, u64 gy2, u64 gy3) {
  u64 rv[N + 6];
#pragma unroll
  for (int i = 0; i < N + 6; i++) rv[i] = bufc[off + i * RP2];
  float acc = 0.f;
#pragma unroll
  for (int i = 0; i < N; i++) {
    u64 D2 = col7(rv, i, gy0, gy1, gy2, gy3);
    u64 e2 = f2mul(f2sub(Dmin2[i], D2), invV2[i]);
    float ep, eg; up2(e2, ep, eg);
    float mp = __expf(ep);
    float mg = __expf(eg);
    if (cOK && (py0 + i) < INNER) acc += fabsf(mp - mg);
  }
  return acc;
}

__device__ __forceinline__ void decode_shift(int si, int& sx, int& sy) {
  int t = si < 55 ? si : si + 1;   // skip (0,0) at index 55
  int q = t / 10;                  // x outer, y inner (matches reference)
  sx = q - 5;
  sy = t - q * 10 - 5;
}

extern "C" __global__ void __launch_bounds__(NTHREADS, 2)
mind_main(const float* __restrict__ pred, const float* __restrict__ gt,
          float* __restrict__ out) {
  extern __shared__ u64 smem[];
  u64* sImg = smem;
  u64* buf[2] = {smem + RH * IP2, smem + RH * IP2 + CHP * RP2};

  const int tX = blockIdx.x, tY = blockIdx.y, b = blockIdx.z;
  const int tid = threadIdx.x;
  const float* imgP = pred + b * HIMG * WIMG;
  const float* imgG = gt + b * HIMG * WIMG;

  // Load tile + halo (circular wrap), interleaving P/G into float2.
  float2* sImgF = (float2*)sImg;
  for (int i = tid; i < RH * RW; i += NTHREADS) {
    int rr = i / RW, c2 = i - rr * RW;
    int gr = tY * TILE_H + rr; if (gr >= HIMG) gr -= HIMG;
    int gc = tX * TILE_W + c2; if (gc >= WIMG) gc -= WIMG;
    sImgF[rr * IP2 + c2] = make_float2(imgP[gr * WIMG + gc],
                                       imgG[gr * WIMG + gc]);
  }
  __syncthreads();

  // Primary row-stage unit (u = tid, rows 0..31): conflict-free mapping.
  const int w0 = tid >> 5, l0 = tid & 31;
  const int j0 = ((l0 >> 3) & 3) | ((w0 & 1) << 2);
  const int r0 = (l0 & 7) | ((w0 >> 1) << 3);
  const u64* paPtr0 = sImg + (r0 + 4) * IP2 + (j0 * 8 + 4);
  u64* pr0B[2] = {buf[0] + r0 * RP2 + j0 * 8, buf[1] + r0 * RP2 + j0 * 8};

  // Overflow unit (rows 32..39), owned by warps 0-1 (tid < 64).
  const bool isRowWarp = tid < 64;   // warps 0,1: row-only role
  const int u1 = tid + NTHREADS;     // unit ids 256..319
  const int w1 = u1 >> 5, l1 = u1 & 31;
  const int j1 = ((l1 >> 3) & 3) | ((w1 & 1) << 2);
  const int r1 = (l1 & 7) | ((w1 >> 1) << 3);
  const u64* paPtr1 = sImg + (r1 + 4) * IP2 + (j1 * 8 + 4);
  u64* pr1B[2] = {buf[0] + r1 * RP2 + j1 * 8, buf[1] + r1 * RP2 + j1 * 8};

  // Cache the primary unit's shift-invariant taps (reused 198 times).
  u64 pa0[14];
#pragma unroll
  for (int k = 0; k < 14; k++) pa0[k] = paPtr0[k];

  // Col-stage ownership (warps 2-7, 192 threads): 64 cols x 3 row groups
  // of {11, 11, 10} rows.
  const int lt = tid - 64;
  const int cc = lt & 63;
  const int gg = lt >> 6;                    // 0..2 (valid when !isRowWarp)
  const int rbase = gg * 11;                 // 0, 11, 22
  const int coff = rbase * RP2 + cc;
  const bool cOK = (tX * TILE_W + cc) < INNER;
  const int py0 = tY * TILE_H + rbase;

  const u64 gx0 = bc2(GX0), gx1 = bc2(GX1), gx2 = bc2(GX2);
  const u64 gy0 = bc2(GY0), gy1 = bc2(GY1), gy2 = bc2(GY2), gy3 = bc2(GY3);

  float DmP[11], DmG[11], Vp[11], Vg[11];
#pragma unroll
  for (int i = 0; i < 11; i++) {
    DmP[i] = 3e38f; DmG[i] = 3e38f; Vp[i] = 0.f; Vg[i] = 0.f;
  }

  int sx, sy;

  // ---------------- Pass A: Dmin and cardinal sum -> invV ----------------
  decode_shift(0, sx, sy);
  {
    int d = sy * IP2 + sx;
    row_cached(pa0, paPtr0 - d, pr0B[0], gx0, gx1, gx2);
    if (isRowWarp) row_smem(paPtr1, paPtr1 - d, pr1B[0], gx0, gx1, gx2);
  }
  __syncthreads();
  for (int si = 0; si < 99; si++) {
    int cur = si & 1;
    if (!isRowWarp) {
      // cardinals: (-1,0)->si45, (0,-1)->si54, (0,1)->si55, (1,0)->si64
      bool card = (si == 45) | (si == 54) | (si == 55) | (si == 64);
      if (gg < 2) colA<11>(buf[cur], coff, card, DmP, DmG, Vp, Vg,
                           gy0, gy1, gy2, gy3);
      else        colA<10>(buf[cur], coff, card, DmP, DmG, Vp, Vg,
                           gy0, gy1, gy2, gy3);
    }
    if (si + 1 < 99) {
      int nsx, nsy;
      decode_shift(si + 1, nsx, nsy);
      int d = nsy * IP2 + nsx;
      row_cached(pa0, paPtr0 - d, pr0B[cur ^ 1], gx0, gx1, gx2);
      if (isRowWarp) row_smem(paPtr1, paPtr1 - d, pr1B[cur ^ 1], gx0, gx1, gx2);
    }
    __syncthreads();
  }
  u64 Dmin2[11], invV2[11];
#pragma unroll
  for (int i = 0; i < 11; i++) {
    Dmin2[i] = pk2(DmP[i], DmG[i]);
    invV2[i] = pk2(1.0f / (Vp[i] * 0.25f + 1e-5f),
                   1.0f / (Vg[i] * 0.25f + 1e-5f));
  }

  // ---------------- Pass B: accumulate |Mp - Mg| ----------------
  float acc = 0.f;
  decode_shift(0, sx, sy);
  {
    int d = sy * IP2 + sx;
    row_cached(pa0, paPtr0 - d, pr0B[0], gx0, gx1, gx2);
    if (isRowWarp) row_smem(paPtr1, paPtr1 - d, pr1B[0], gx0, gx1, gx2);
  }
  __syncthreads();
  for (int si = 0; si < 99; si++) {
    int cur = si & 1;
    if (!isRowWarp) {
      if (gg < 2) acc += colB<11>(buf[cur], coff, Dmin2, invV2, py0, cOK,
                                  gy0, gy1, gy2, gy3);
      else        acc += colB<10>(buf[cur], coff, Dmin2, invV2, py0, cOK,
                                  gy0, gy1, gy2, gy3);
    }
    if (si + 1 < 99) {
      int nsx, nsy;
      decode_shift(si + 1, nsx, nsy);
      int d = nsy * IP2 + nsx;
      row_cached(pa0, paPtr0 - d, pr0B[cur ^ 1], gx0, gx1, gx2);
      if (isRowWarp) row_smem(paPtr1, paPtr1 - d, pr1B[cur ^ 1], gx0, gx1, gx2);
    }
    __syncthreads();
  }

  // ---------------- Per-CTA reduction (deterministic) ----------------
#pragma unroll
  for (int o = 16; o > 0; o >>= 1) acc += __shfl_down_sync(0xffffffffu, acc, o);
  float* red = (float*)smem;   // passes done; safe reuse
  if ((tid & 31) == 0) red[tid >> 5] = acc;
  __syncthreads();
  const int ctaIdx = (b * TILES_Y + tY) * TILES_X + tX;
  if (tid == 0) {
    float s = 0.f;
#pragma unroll
    for (int ww = 0; ww < NTHREADS / 32; ww++) s += red[ww];
    g_partials[ctaIdx] = s;
    __threadfence();
    unsigned int old = atomicAdd(&g_count, 1u);
    red[8] = (old == NCTAS - 1) ? 1.f : 0.f;
  }
  __syncthreads();

  // ---------------- Last CTA: global reduction ----------------
  if (red[8] != 0.f) {
    __threadfence();
    float s = g_partials[tid];
    if (tid < NCTAS - NTHREADS) s += g_partials[tid + NTHREADS];
#pragma unroll
    for (int o = 16; o > 0; o >>= 1) s += __shfl_down_sync(0xffffffffu, s, o);
    __syncthreads();
    if ((tid & 31) == 0) red[tid >> 5] = s;
    __syncthreads();
    if (tid == 0) {
      float t = 0.f;
#pragma unroll
      for (int ww = 0; ww < NTHREADS / 32; ww++) t += red[ww];
      out[0] = t * (float)(1.0 / ((double)BATCH * INNER * INNER * 99.0));
      g_count = 0;   // reset for next graph replay
    }
  }
}

extern "C" void kernel_launch(void* const* d_in, const int* in_sizes, int n_in,
                              void* d_out, int out_size) {
  const float* pred = (const float*)d_in[0];
  const float* gt = (const float*)d_in[1];
  cudaFuncSetAttribute(mind_main, cudaFuncAttributeMaxDynamicSharedMemorySize,
                       SMEM_BYTES);
  dim3 grid(TILES_X, TILES_Y, BATCH);
  mind_main<<<grid, NTHREADS, SMEM_BYTES>>>(pred, gt, (float*)d_out);
}

// round 7
// speedup vs baseline: 1.0015x; 1.0015x over previous
#include <cuda_runtime.h>

// ---------------------------------------------------------------------------
// MIND loss, fully fused, single kernel. R6:
//  - role-specialized warps: warps 0-1 = row-stage only (incl. 64 overflow
//    units), warps 2-7 = row unit + all column/epilogue work (rows 11/11/10)
//    -> balanced per-warp time at each __syncthreads
//  - last-CTA global reduction folded in (deterministic fixed-order sum)
//  - pred/gt packed into f32x2 (FFMA2); conflict-free 64-bit smem (81/67)
//  - M/max(M) == exp((Dmin - D)/V) -> two passes over the 99 shifts
// ---------------------------------------------------------------------------

typedef unsigned long long u64;

namespace {
constexpr int HIMG = 384;
constexpr int WIMG = 384;
constexpr int BATCH = 4;
constexpr int INNER = 370;          // 384 - 2*7
constexpr int TILE_H = 32;
constexpr int TILE_W = 64;
constexpr int CHP = 40;             // conv-support rows (38 used + 2 pad)
constexpr int RH = 49;              // img tile rows
constexpr int RW = 79;              // img tile cols
constexpr int IP2 = 81;             // img pitch (float2 units, odd)
constexpr int RP2 = 67;             // row-buf pitch (float2 units, odd)
constexpr int NTHREADS = 256;
constexpr int TILES_X = 6;          // 6*64 = 384 >= 370
constexpr int TILES_Y = 12;         // 12*32 = 384 >= 370
constexpr int NCTAS = BATCH * TILES_X * TILES_Y;   // 288 -> one wave @ occ 2
constexpr int SMEM_U64 = RH * IP2 + 2 * CHP * RP2;
constexpr int SMEM_BYTES = SMEM_U64 * 8;           // 74632 B

constexpr double E98 = 0.32465246735834974;   // exp(-9/8)
constexpr double E48 = 0.60653065971263342;   // exp(-4/8)
constexpr double E18 = 0.88249690258459546;   // exp(-1/8)
constexpr double TPS = 25.132741228718345;    // 8*pi
constexpr float GX0 = (float)E98;
constexpr float GX1 = (float)E48;
constexpr float GX2 = (float)E18;             // center tap == 1
constexpr float GY0 = (float)(E98 / TPS);
constexpr float GY1 = (float)(E48 / TPS);
constexpr float GY2 = (float)(E18 / TPS);
constexpr float GY3 = (float)(1.0 / TPS);
}  // namespace

__device__ float g_partials[NCTAS];
__device__ unsigned int g_count = 0;

// ---- packed f32x2 helpers (sm_100+) ----
__device__ __forceinline__ u64 bc2(float x) {
  u64 r; asm("mov.b64 %0,{%1,%1};" : "=l"(r) : "f"(x)); return r;
}
__device__ __forceinline__ u64 pk2(float a, float b) {
  u64 r; asm("mov.b64 %0,{%1,%2};" : "=l"(r) : "f"(a), "f"(b)); return r;
}
__device__ __forceinline__ void up2(u64 v, float& a, float& b) {
  asm("mov.b64 {%0,%1},%2;" : "=f"(a), "=f"(b) : "l"(v));
}
__device__ __forceinline__ u64 f2sub(u64 a, u64 b) {
  u64 r; asm("sub.rn.f32x2 %0,%1,%2;" : "=l"(r) : "l"(a), "l"(b)); return r;
}
__device__ __forceinline__ u64 f2mul(u64 a, u64 b) {
  u64 r; asm("mul.rn.f32x2 %0,%1,%2;" : "=l"(r) : "l"(a), "l"(b)); return r;
}
__device__ __forceinline__ u64 f2add(u64 a, u64 b) {
  u64 r; asm("add.rn.f32x2 %0,%1,%2;" : "=l"(r) : "l"(a), "l"(b)); return r;
}
__device__ __forceinline__ u64 f2fma(u64 a, u64 b, u64 c) {
  u64 r; asm("fma.rn.f32x2 %0,%1,%2,%3;" : "=l"(r) : "l"(a), "l"(b), "l"(c));
  return r;
}

// Horizontal 7-tap conv over precomputed dsq -> 8 outputs.
__device__ __forceinline__ void hconv8(const u64 dsq[14], u64* __restrict__ pr,
                                       u64 gx0, u64 gx1, u64 gx2) {
#pragma unroll
  for (int c = 0; c < 8; c++) {
    u64 v = f2mul(gx0, dsq[c]);
    v = f2fma(gx1, dsq[c + 1], v);
    v = f2fma(gx2, dsq[c + 2], v);
    v = f2add(v, dsq[c + 3]);  // center tap weight == 1
    v = f2fma(gx2, dsq[c + 4], v);
    v = f2fma(gx1, dsq[c + 5], v);
    v = f2fma(gx0, dsq[c + 6], v);
    pr[c] = v;
  }
}

__device__ __forceinline__ void row_cached(const u64 pa[14],
                                           const u64* __restrict__ pb,
                                           u64* __restrict__ pr,
                                           u64 gx0, u64 gx1, u64 gx2) {
  u64 dsq[14];
#pragma unroll
  for (int k = 0; k < 14; k++) {
    u64 d = f2sub(pa[k], pb[k]);
    dsq[k] = f2mul(d, d);
  }
  hconv8(dsq, pr, gx0, gx1, gx2);
}

__device__ __forceinline__ void row_smem(const u64* __restrict__ pa,
                                         const u64* __restrict__ pb,
                                         u64* __restrict__ pr,
                                         u64 gx0, u64 gx1, u64 gx2) {
  u64 dsq[14];
#pragma unroll
  for (int k = 0; k < 14; k++) {
    u64 d = f2sub(pa[k], pb[k]);
    dsq[k] = f2mul(d, d);
  }
  hconv8(dsq, pr, gx0, gx1, gx2);
}

__device__ __forceinline__ u64 col7(const u64* rv, int i,
                                    u64 gy0, u64 gy1, u64 gy2, u64 gy3) {
  u64 v = f2mul(gy0, rv[i]);
  v = f2fma(gy1, rv[i + 1], v);
  v = f2fma(gy2, rv[i + 2], v);
  v = f2fma(gy3, rv[i + 3], v);
  v = f2fma(gy2, rv[i + 4], v);
  v = f2fma(gy1, rv[i + 5], v);
  v = f2fma(gy0, rv[i + 6], v);
  return v;
}

template <int N>
__device__ __forceinline__ void colA(const u64* __restrict__ bufc, int off,
                                     bool card, float* DmP, float* DmG,
                                     float* Vp, float* Vg,
                                     u64 gy0, u64 gy1, u64 gy2, u64 gy3) {
  u64 rv[N + 6];
#pragma unroll
  for (int i = 0; i < N + 6; i++) rv[i] = bufc[off + i * RP2];
#pragma unroll
  for (int i = 0; i < N; i++) {
    u64 D2 = col7(rv, i, gy0, gy1, gy2, gy3);
    float dp, dg; up2(D2, dp, dg);
    DmP[i] = fminf(DmP[i], dp);
    DmG[i] = fminf(DmG[i], dg);
    if (card) { Vp[i] += dp; Vg[i] += dg; }
  }
}

template <int N>
__device__ __forceinline__ float colB(const u64* __restrict__ bufc, int off,
                                      const u64* Dmin2, const u64* invV2,
                                      int py0, bool cOK,
                                      u64 gy0, u64 gy1, u64 gy2, u64 gy3) {
  u64 rv[N + 6];
#pragma unroll
  for (int i = 0; i < N + 6; i++) rv[i] = bufc[off + i * RP2];
  float acc = 0.f;
#pragma unroll
  for (int i = 0; i < N; i++) {
    u64 D2 = col7(rv, i, gy0, gy1, gy2, gy3);
    u64 e2 = f2mul(f2sub(Dmin2[i], D2), invV2[i]);
    float ep, eg; up2(e2, ep, eg);
    float mp = __expf(ep);
    float mg = __expf(eg);
    if (cOK && (py0 + i) < INNER) acc += fabsf(mp - mg);
  }
  return acc;
}

__device__ __forceinline__ void decode_shift(int si, int& sx, int& sy) {
  int t = si < 55 ? si : si + 1;   // skip (0,0) at index 55
  int q = t / 10;                  // x outer, y inner (matches reference)
  sx = q - 5;
  sy = t - q * 10 - 5;
}

extern "C" __global__ void __launch_bounds__(NTHREADS, 2)
mind_main(const float* __restrict__ pred, const float* __restrict__ gt,
          float* __restrict__ out) {
  extern __shared__ u64 smem[];
  u64* sImg = smem;
  u64* buf[2] = {smem + RH * IP2, smem + RH * IP2 + CHP * RP2};

  const int tX = blockIdx.x, tY = blockIdx.y, b = blockIdx.z;
  const int tid = threadIdx.x;
  const float* imgP = pred + b * HIMG * WIMG;
  const float* imgG = gt + b * HIMG * WIMG;

  // Load tile + halo (circular wrap), interleaving P/G into float2.
  float2* sImgF = (float2*)sImg;
  for (int i = tid; i < RH * RW; i += NTHREADS) {
    int rr = i / RW, c2 = i - rr * RW;
    int gr = tY * TILE_H + rr; if (gr >= HIMG) gr -= HIMG;
    int gc = tX * TILE_W + c2; if (gc >= WIMG) gc -= WIMG;
    sImgF[rr * IP2 + c2] = make_float2(imgP[gr * WIMG + gc],
                                       imgG[gr * WIMG + gc]);
  }
  __syncthreads();

  // Primary row-stage unit (u = tid, rows 0..31): conflict-free mapping.
  const int w0 = tid >> 5, l0 = tid & 31;
  const int j0 = ((l0 >> 3) & 3) | ((w0 & 1) << 2);
  const int r0 = (l0 & 7) | ((w0 >> 1) << 3);
  const u64* paPtr0 = sImg + (r0 + 4) * IP2 + (j0 * 8 + 4);
  u64* pr0B[2] = {buf[0] + r0 * RP2 + j0 * 8, buf[1] + r0 * RP2 + j0 * 8};

  // Overflow unit (rows 32..39), owned by warps 0-1 (tid < 64).
  const bool isRowWarp = tid < 64;   // warps 0,1: row-only role
  const int u1 = tid + NTHREADS;     // unit ids 256..319
  const int w1 = u1 >> 5, l1 = u1 & 31;
  const int j1 = ((l1 >> 3) & 3) | ((w1 & 1) << 2);
  const int r1 = (l1 & 7) | ((w1 >> 1) << 3);
  const u64* paPtr1 = sImg + (r1 + 4) * IP2 + (j1 * 8 + 4);
  u64* pr1B[2] = {buf[0] + r1 * RP2 + j1 * 8, buf[1] + r1 * RP2 + j1 * 8};

  // Cache the primary unit's shift-invariant taps (reused 198 times).
  u64 pa0[14];
#pragma unroll
  for (int k = 0; k < 14; k++) pa0[k] = paPtr0[k];

  // Col-stage ownership (warps 2-7, 192 threads): 64 cols x 3 row groups
  // of {11, 11, 10} rows.
  const int lt = tid - 64;
  const int cc = lt & 63;
  const int gg = lt >> 6;                    // 0..2 (valid when !isRowWarp)
  const int rbase = gg * 11;                 // 0, 11, 22
  const int coff = rbase * RP2 + cc;
  const bool cOK = (tX * TILE_W + cc) < INNER;
  const int py0 = tY * TILE_H + rbase;

  const u64 gx0 = bc2(GX0), gx1 = bc2(GX1), gx2 = bc2(GX2);
  const u64 gy0 = bc2(GY0), gy1 = bc2(GY1), gy2 = bc2(GY2), gy3 = bc2(GY3);

  float DmP[11], DmG[11], Vp[11], Vg[11];
#pragma unroll
  for (int i = 0; i < 11; i++) {
    DmP[i] = 3e38f; DmG[i] = 3e38f; Vp[i] = 0.f; Vg[i] = 0.f;
  }

  int sx, sy;

  // ---------------- Pass A: Dmin and cardinal sum -> invV ----------------
  decode_shift(0, sx, sy);
  {
    int d = sy * IP2 + sx;
    row_cached(pa0, paPtr0 - d, pr0B[0], gx0, gx1, gx2);
    if (isRowWarp) row_smem(paPtr1, paPtr1 - d, pr1B[0], gx0, gx1, gx2);
  }
  __syncthreads();
  for (int si = 0; si < 99; si++) {
    int cur = si & 1;
    if (!isRowWarp) {
      // cardinals: (-1,0)->si45, (0,-1)->si54, (0,1)->si55, (1,0)->si64
      bool card = (si == 45) | (si == 54) | (si == 55) | (si == 64);
      if (gg < 2) colA<11>(buf[cur], coff, card, DmP, DmG, Vp, Vg,
                           gy0, gy1, gy2, gy3);
      else        colA<10>(buf[cur], coff, card, DmP, DmG, Vp, Vg,
                           gy0, gy1, gy2, gy3);
    }
    if (si + 1 < 99) {
      int nsx, nsy;
      decode_shift(si + 1, nsx, nsy);
      int d = nsy * IP2 + nsx;
      row_cached(pa0, paPtr0 - d, pr0B[cur ^ 1], gx0, gx1, gx2);
      if (isRowWarp) row_smem(paPtr1, paPtr1 - d, pr1B[cur ^ 1], gx0, gx1, gx2);
    }
    __syncthreads();
  }
  u64 Dmin2[11], invV2[11];
#pragma unroll
  for (int i = 0; i < 11; i++) {
    Dmin2[i] = pk2(DmP[i], DmG[i]);
    invV2[i] = pk2(1.0f / (Vp[i] * 0.25f + 1e-5f),
                   1.0f / (Vg[i] * 0.25f + 1e-5f));
  }

  // ---------------- Pass B: accumulate |Mp - Mg| ----------------
  float acc = 0.f;
  decode_shift(0, sx, sy);
  {
    int d = sy * IP2 + sx;
    row_cached(pa0, paPtr0 - d, pr0B[0], gx0, gx1, gx2);
    if (isRowWarp) row_smem(paPtr1, paPtr1 - d, pr1B[0], gx0, gx1, gx2);
  }
  __syncthreads();
  for (int si = 0; si < 99; si++) {
    int cur = si & 1;
    if (!isRowWarp) {
      if (gg < 2) acc += colB<11>(buf[cur], coff, Dmin2, invV2, py0, cOK,
                                  gy0, gy1, gy2, gy3);
      else        acc += colB<10>(buf[cur], coff, Dmin2, invV2, py0, cOK,
                                  gy0, gy1, gy2, gy3);
    }
    if (si + 1 < 99) {
      int nsx, nsy;
      decode_shift(si + 1, nsx, nsy);
      int d = nsy * IP2 + nsx;
      row_cached(pa0, paPtr0 - d, pr0B[cur ^ 1], gx0, gx1, gx2);
      if (isRowWarp) row_smem(paPtr1, paPtr1 - d, pr1B[cur ^ 1], gx0, gx1, gx2);
    }
    __syncthreads();
  }

  // ---------------- Per-CTA reduction (deterministic) ----------------
#pragma unroll
  for (int o = 16; o > 0; o >>= 1) acc += __shfl_down_sync(0xffffffffu, acc, o);
  float* red = (float*)smem;   // passes done; safe reuse
  if ((tid & 31) == 0) red[tid >> 5] = acc;
  __syncthreads();
  const int ctaIdx = (b * TILES_Y + tY) * TILES_X + tX;
  if (tid == 0) {
    float s = 0.f;
#pragma unroll
    for (int ww = 0; ww < NTHREADS / 32; ww++) s += red[ww];
    g_partials[ctaIdx] = s;
    __threadfence();
    unsigned int old = atomicAdd(&g_count, 1u);
    red[8] = (old == NCTAS - 1) ? 1.f : 0.f;
  }
  __syncthreads();

  // ---------------- Last CTA: global reduction ----------------
  if (red[8] != 0.f) {
    __threadfence();
    float s = g_partials[tid];
    if (tid < NCTAS - NTHREADS) s += g_partials[tid + NTHREADS];
#pragma unroll
    for (int o = 16; o > 0; o >>= 1) s += __shfl_down_sync(0xffffffffu, s, o);
    __syncthreads();
    if ((tid & 31) == 0) red[tid >> 5] = s;
    __syncthreads();
    if (tid == 0) {
      float t = 0.f;
#pragma unroll
      for (int ww = 0; ww < NTHREADS / 32; ww++) t += red[ww];
      out[0] = t * (float)(1.0 / ((double)BATCH * INNER * INNER * 99.0));
      g_count = 0;   // reset for next graph replay
    }
  }
}

extern "C" void kernel_launch(void* const* d_in, const int* in_sizes, int n_in,
                              void* d_out, int out_size) {
  const float* pred = (const float*)d_in[0];
  const float* gt = (const float*)d_in[1];
  cudaFuncSetAttribute(mind_main, cudaFuncAttributeMaxDynamicSharedMemorySize,
                       SMEM_BYTES);
  dim3 grid(TILES_X, TILES_Y, BATCH);
  mind_main<<<grid, NTHREADS, SMEM_BYTES>>>(pred, gt, (float*)d_out);
}

// round 8
// speedup vs baseline: 1.2698x; 1.2679x over previous
#include <cuda_runtime.h>

// ---------------------------------------------------------------------------
// MIND loss, fully fused, single kernel. R8: +/- shift pairing.
//   dsq_{-s}(q) == dsq_s(q+s) bitwise, conv is shift-equivariant, so
//   D_{-s}(p) == C_s(p+s): one extended row-conv field (42 x 72, width-12
//   units -> exactly 252 = one per thread) serves both shifts of a pair.
//   40 pairs + 19 singles = 59 barrier intervals per pass (vs 99).
//  - pred/gt packed into f32x2 (FFMA2); odd smem pitches (87/73 mod 16
//    coprime) keep 64-bit accesses conflict-free per 16-lane phase
//  - M/max(M) == exp((Dmin - D)/V) -> two passes over the shift events
//  - V accumulated in the reference's exact fp order (events 0 and 8)
//  - in-kernel deterministic last-CTA reduction
// ---------------------------------------------------------------------------

typedef unsigned long long u64;

namespace {
constexpr int HIMG = 384;
constexpr int WIMG = 384;
constexpr int BATCH = 4;
constexpr int INNER = 370;          // 384 - 2*7
constexpr int TILE_H = 32;
constexpr int TILE_W = 64;
constexpr int RH = 47;              // img tile rows (q_r in [-7, 39])
constexpr int RW = 86;              // img tile cols (q_c in [-11, 74])
constexpr int IP = 87;              // img pitch (87 mod 16 = 7, coprime)
constexpr int BROWS = 42;           // buffer rows (q_r in [-3, 38])
constexpr int BP = 73;              // buffer pitch (73 mod 16 = 9, coprime)
constexpr int NTHREADS = 256;
constexpr int TILES_X = 6;
constexpr int TILES_Y = 12;
constexpr int NCTAS = BATCH * TILES_X * TILES_Y;   // 288 -> one wave @ occ 2
constexpr int SMEM_U64 = RH * IP + 2 * BROWS * BP; // 4089 + 6132 = 10221
constexpr int SMEM_BYTES = SMEM_U64 * 8;           // 81768 B
constexpr int NEVENTS = 59;                        // 40 pairs + 19 singles

constexpr double E98 = 0.32465246735834974;   // exp(-9/8)
constexpr double E48 = 0.60653065971263342;   // exp(-4/8)
constexpr double E18 = 0.88249690258459546;   // exp(-1/8)
constexpr double TPS = 25.132741228718345;    // 8*pi
constexpr float GX0 = (float)E98;
constexpr float GX1 = (float)E48;
constexpr float GX2 = (float)E18;             // center tap == 1
constexpr float GY0 = (float)(E98 / TPS);
constexpr float GY1 = (float)(E48 / TPS);
constexpr float GY2 = (float)(E18 / TPS);
constexpr float GY3 = (float)(1.0 / TPS);
}  // namespace

__device__ float g_partials[NCTAS];
__device__ unsigned int g_count = 0;

// ---- packed f32x2 helpers (sm_100+) ----
__device__ __forceinline__ u64 bcast2(float x) {
  u64 r; asm("mov.b64 %0,{%1,%1};" : "=l"(r) : "f"(x)); return r;
}
__device__ __forceinline__ u64 pk2(float a, float b) {
  u64 r; asm("mov.b64 %0,{%1,%2};" : "=l"(r) : "f"(a), "f"(b)); return r;
}
__device__ __forceinline__ void up2(u64 v, float& a, float& b) {
  asm("mov.b64 {%0,%1},%2;" : "=f"(a), "=f"(b) : "l"(v));
}
__device__ __forceinline__ u64 f2sub(u64 a, u64 b) {
  u64 r; asm("sub.rn.f32x2 %0,%1,%2;" : "=l"(r) : "l"(a), "l"(b)); return r;
}
__device__ __forceinline__ u64 f2mul(u64 a, u64 b) {
  u64 r; asm("mul.rn.f32x2 %0,%1,%2;" : "=l"(r) : "l"(a), "l"(b)); return r;
}
__device__ __forceinline__ u64 f2add(u64 a, u64 b) {
  u64 r; asm("add.rn.f32x2 %0,%1,%2;" : "=l"(r) : "l"(a), "l"(b)); return r;
}
__device__ __forceinline__ u64 f2fma(u64 a, u64 b, u64 c) {
  u64 r; asm("fma.rn.f32x2 %0,%1,%2,%3;" : "=l"(r) : "l"(a), "l"(b), "l"(c));
  return r;
}

// Event schedule. e<40: pair representatives (sy>0, or sy==0 && sx>=1);
// each also yields -s. e in [40,50): sx=-5 singles; [50,59): sy=-5 singles.
// Pair (1,0) at e=0 and (0,1) at e=8 -> V accumulates in reference order.
__device__ __forceinline__ void decode_event(int e, int& sx, int& sy,
                                             bool& pair) {
  if (e < 4)       { sx = e + 1;               sy = 0;           pair = true; }
  else if (e < 40) { int t = e - 4; sy = 1 + t / 9; sx = t % 9 - 4;
                     pair = true; }
  else if (e < 50) { sx = -5;                  sy = (e - 40) - 5; pair = false; }
  else             { sy = -5;                  sx = (e - 50) - 4; pair = false; }
}

// Fused diffsq + horizontal 7-tap conv: one width-12 unit (18 taps -> 12).
// Unit (r1, j1): buffer row r1 (q_r = r1-3), buffer cols [j1, j1+12).
__device__ __forceinline__ void produce_unit(const u64* __restrict__ sImg,
                                             u64* __restrict__ Bdst,
                                             int r1, int j1, int sx, int sy,
                                             u64 gx0, u64 gx1, u64 gx2) {
  const u64* pa = sImg + (r1 + 4) * IP + (j1 + 4);
  const u64* pb = sImg + (r1 + 4 - sy) * IP + (j1 + 4 - sx);
  u64 dsq[18];
#pragma unroll
  for (int k = 0; k < 18; k++) {
    u64 d = f2sub(pa[k], pb[k]);
    dsq[k] = f2mul(d, d);
  }
  u64* pr = Bdst + r1 * BP + j1;
#pragma unroll
  for (int c = 0; c < 12; c++) {
    u64 v = f2mul(gx0, dsq[c]);
    v = f2fma(gx1, dsq[c + 1], v);
    v = f2fma(gx2, dsq[c + 2], v);
    v = f2add(v, dsq[c + 3]);  // center tap weight == 1
    v = f2fma(gx2, dsq[c + 4], v);
    v = f2fma(gx1, dsq[c + 5], v);
    v = f2fma(gx0, dsq[c + 6], v);
    pr[c] = v;
  }
}

__device__ __forceinline__ u64 col7(const u64* rv, int i,
                                    u64 gy0, u64 gy1, u64 gy2, u64 gy3) {
  u64 v = f2mul(gy0, rv[i]);
  v = f2fma(gy1, rv[i + 1], v);
  v = f2fma(gy2, rv[i + 2], v);
  v = f2fma(gy3, rv[i + 3], v);
  v = f2fma(gy2, rv[i + 4], v);
  v = f2fma(gy1, rv[i + 5], v);
  v = f2fma(gy0, rv[i + 6], v);
  return v;
}

extern "C" __global__ void __launch_bounds__(NTHREADS, 2)
mind_main(const float* __restrict__ pred, const float* __restrict__ gt,
          float* __restrict__ out) {
  extern __shared__ u64 smem[];
  u64* sImg = smem;
  u64* buf[2] = {smem + RH * IP, smem + RH * IP + BROWS * BP};

  const int tX = blockIdx.x, tY = blockIdx.y, b = blockIdx.z;
  const int tid = threadIdx.x;
  const float* imgP = pred + b * HIMG * WIMG;
  const float* imgG = gt + b * HIMG * WIMG;

  // Load tile + halo (circular wrap). abs row = tY*32 + mr,
  // abs col = tX*64 + mc - 4 (both mod 384).
  float2* sImgF = (float2*)sImg;
  for (int i = tid; i < RH * RW; i += NTHREADS) {
    int mr = i / RW, mc = i - mr * RW;
    int gr = tY * TILE_H + mr; if (gr >= HIMG) gr -= HIMG;
    int gc = tX * TILE_W + mc - 4;
    if (gc < 0) gc += WIMG;
    if (gc >= WIMG) gc -= WIMG;
    sImgF[mr * IP + mc] = make_float2(imgP[gr * WIMG + gc],
                                      imgG[gr * WIMG + gc]);
  }
  __syncthreads();

  // Row-stage: 252 width-12 units = 42 buffer rows x 6 blocks.
  const bool rowAct = tid < 252;
  const int r1 = tid % 42;
  const int j1 = (tid / 42) * 12;

  // Col-stage: 64 cols x 4 groups of 8 rows (all 256 threads).
  const int cc = tid & 63;
  const int gg = tid >> 6;
  const int rbase = gg * 8;
  const int cc4 = cc + 4;           // buffer col of pixel col cc
  const bool cOK = (tX * TILE_W + cc) < INNER;
  const int py0 = tY * TILE_H + rbase;

  const u64 gx0 = bcast2(GX0), gx1 = bcast2(GX1), gx2 = bcast2(GX2);
  const u64 gy0 = bcast2(GY0), gy1 = bcast2(GY1), gy2 = bcast2(GY2),
            gy3 = bcast2(GY3);

  float DmP[8], DmG[8], Vp[8], Vg[8];
#pragma unroll
  for (int i = 0; i < 8; i++) {
    DmP[i] = 3e38f; DmG[i] = 3e38f; Vp[i] = 0.f; Vg[i] = 0.f;
  }

  int sx, sy; bool isPair;

  // ---------------- Pass A: Dmin and cardinal sum -> invV ----------------
  decode_event(0, sx, sy, isPair);
  if (rowAct) produce_unit(sImg, buf[0], r1, j1, sx, sy, gx0, gx1, gx2);
  __syncthreads();
  for (int e = 0; e < NEVENTS; e++) {
    int cur = e & 1;
    decode_event(e, sx, sy, isPair);
    const u64* bc = buf[cur];
    u64 rv[14];
#pragma unroll
    for (int i = 0; i < 14; i++) rv[i] = bc[(rbase + i) * BP + cc4];
    if (isPair) {
      u64 D1[8];
#pragma unroll
      for (int i = 0; i < 8; i++) D1[i] = col7(rv, i, gy0, gy1, gy2, gy3);
      const u64* bp2 = bc + sy * BP + sx;
#pragma unroll
      for (int i = 0; i < 14; i++) rv[i] = bp2[(rbase + i) * BP + cc4];
#pragma unroll
      for (int i = 0; i < 8; i++) {
        u64 D2 = col7(rv, i, gy0, gy1, gy2, gy3);
        float dp1, dg1, dp2, dg2;
        up2(D1[i], dp1, dg1); up2(D2, dp2, dg2);
        DmP[i] = fminf(fminf(DmP[i], dp1), dp2);
        DmG[i] = fminf(fminf(DmG[i], dg1), dg2);
        if (e == 0) {            // pair (1,0): V = D(-1,0) + D(1,0)
          Vp[i] = dp2 + dp1; Vg[i] = dg2 + dg1;
        } else if (e == 8) {     // pair (0,1): V = (V + D(0,-1)) + D(0,1)
          Vp[i] = (Vp[i] + dp2) + dp1; Vg[i] = (Vg[i] + dg2) + dg1;
        }
      }
    } else {
#pragma unroll
      for (int i = 0; i < 8; i++) {
        u64 D1 = col7(rv, i, gy0, gy1, gy2, gy3);
        float dp1, dg1; up2(D1, dp1, dg1);
        DmP[i] = fminf(DmP[i], dp1);
        DmG[i] = fminf(DmG[i], dg1);
      }
    }
    if (e + 1 < NEVENTS) {
      int nsx, nsy; bool npair;
      decode_event(e + 1, nsx, nsy, npair);
      if (rowAct && (npair || r1 < 38))
        produce_unit(sImg, buf[cur ^ 1], r1, j1, nsx, nsy, gx0, gx1, gx2);
    }
    __syncthreads();
  }
  u64 Dmin2[8], invV2[8];
#pragma unroll
  for (int i = 0; i < 8; i++) {
    Dmin2[i] = pk2(DmP[i], DmG[i]);
    invV2[i] = pk2(1.0f / (Vp[i] * 0.25f + 1e-5f),
                   1.0f / (Vg[i] * 0.25f + 1e-5f));
  }

  // ---------------- Pass B: accumulate |Mp - Mg| ----------------
  float acc = 0.f;
  decode_event(0, sx, sy, isPair);
  if (rowAct) produce_unit(sImg, buf[0], r1, j1, sx, sy, gx0, gx1, gx2);
  __syncthreads();
  for (int e = 0; e < NEVENTS; e++) {
    int cur = e & 1;
    decode_event(e, sx, sy, isPair);
    const u64* bc = buf[cur];
    u64 rv[14];
#pragma unroll
    for (int i = 0; i < 14; i++) rv[i] = bc[(rbase + i) * BP + cc4];
    float lacc = 0.f;
    if (isPair) {
      u64 D1[8];
#pragma unroll
      for (int i = 0; i < 8; i++) D1[i] = col7(rv, i, gy0, gy1, gy2, gy3);
      const u64* bp2 = bc + sy * BP + sx;
#pragma unroll
      for (int i = 0; i < 14; i++) rv[i] = bp2[(rbase + i) * BP + cc4];
#pragma unroll
      for (int i = 0; i < 8; i++) {
        u64 D2 = col7(rv, i, gy0, gy1, gy2, gy3);
        u64 e1 = f2mul(f2sub(Dmin2[i], D1[i]), invV2[i]);
        u64 e2 = f2mul(f2sub(Dmin2[i], D2), invV2[i]);
        float a1, b1, a2, b2;
        up2(e1, a1, b1); up2(e2, a2, b2);
        float t = fabsf(__expf(a1) - __expf(b1)) +
                  fabsf(__expf(a2) - __expf(b2));
        if ((py0 + i) < INNER) lacc += t;
      }
    } else {
#pragma unroll
      for (int i = 0; i < 8; i++) {
        u64 D1 = col7(rv, i, gy0, gy1, gy2, gy3);
        u64 e1 = f2mul(f2sub(Dmin2[i], D1), invV2[i]);
        float a1, b1; up2(e1, a1, b1);
        float t = fabsf(__expf(a1) - __expf(b1));
        if ((py0 + i) < INNER) lacc += t;
      }
    }
    if (cOK) acc += lacc;
    if (e + 1 < NEVENTS) {
      int nsx, nsy; bool npair;
      decode_event(e + 1, nsx, nsy, npair);
      if (rowAct && (npair || r1 < 38))
        produce_unit(sImg, buf[cur ^ 1], r1, j1, nsx, nsy, gx0, gx1, gx2);
    }
    __syncthreads();
  }

  // ---------------- Per-CTA reduction (deterministic) ----------------
#pragma unroll
  for (int o = 16; o > 0; o >>= 1) acc += __shfl_down_sync(0xffffffffu, acc, o);
  float* red = (float*)smem;   // passes done; safe reuse
  if ((tid & 31) == 0) red[tid >> 5] = acc;
  __syncthreads();
  const int ctaIdx = (b * TILES_Y + tY) * TILES_X + tX;
  if (tid == 0) {
    float s = 0.f;
#pragma unroll
    for (int ww = 0; ww < NTHREADS / 32; ww++) s += red[ww];
    g_partials[ctaIdx] = s;
    __threadfence();
    unsigned int old = atomicAdd(&g_count, 1u);
    red[8] = (old == NCTAS - 1) ? 1.f : 0.f;
  }
  __syncthreads();

  // ---------------- Last CTA: global reduction ----------------
  if (red[8] != 0.f) {
    __threadfence();
    float s = g_partials[tid];
    if (tid < NCTAS - NTHREADS) s += g_partials[tid + NTHREADS];
#pragma unroll
    for (int o = 16; o > 0; o >>= 1) s += __shfl_down_sync(0xffffffffu, s, o);
    __syncthreads();
    if ((tid & 31) == 0) red[tid >> 5] = s;
    __syncthreads();
    if (tid == 0) {
      float t = 0.f;
#pragma unroll
      for (int ww = 0; ww < NTHREADS / 32; ww++) t += red[ww];
      out[0] = t * (float)(1.0 / ((double)BATCH * INNER * INNER * 99.0));
      g_count = 0;   // reset for next graph replay
    }
  }
}

extern "C" void kernel_launch(void* const* d_in, const int* in_sizes, int n_in,
                              void* d_out, int out_size) {
  const float* pred = (const float*)d_in[0];
  const float* gt = (const float*)d_in[1];
  cudaFuncSetAttribute(mind_main, cudaFuncAttributeMaxDynamicSharedMemorySize,
                       SMEM_BYTES);
  dim3 grid(TILES_X, TILES_Y, BATCH);
  mind_main<<<grid, NTHREADS, SMEM_BYTES>>>(pred, gt, (float*)d_out);
}